// round 16
// baseline (speedup 1.0000x reference)
#include <cuda_runtime.h>
#include <cuda_fp16.h>
#include <cstdint>

#define U_UNITS 2048
#define T_STEPS 512
#define B_BATCH 32
#define D_INPUT 128
#define RHO_C   0.99f

#define NCHUNK        8
#define B_PER_CHUNK   (B_BATCH / NCHUNK)        // 4 batches
#define M_PER_CHUNK   (B_PER_CHUNK * T_STEPS)   // 2048 rows
#define GEMM_PER_CHUNK 256                      // 16 x 16 tiles
#define SCAN_PER_CHUNK 32                       // 8192 threads / 256
#define BLK_PER_CHUNK (GEMM_PER_CHUNK + SCAN_PER_CHUNK)   // 288

// per-chunk completion counters (zeroed by init kernel each call)
__device__ int g_ctr[NCHUNK];

// ======================= GEMM pieces =======================
#define BM 128
#define BN 128
#define SSTRIDE 136                       // fp16 elems per smem row (128 + 8 pad)
#define TILE_BYTES (128 * SSTRIDE * 2)    // 34816 B

__device__ __forceinline__ uint32_t smem_u32(const void* p) {
    return (uint32_t)__cvta_generic_to_shared(p);
}
__device__ __forceinline__ void ldsm_x4(uint32_t* r, uint32_t a) {
    asm volatile("ldmatrix.sync.aligned.m8n8.x4.shared.b16 {%0,%1,%2,%3}, [%4];"
                 : "=r"(r[0]), "=r"(r[1]), "=r"(r[2]), "=r"(r[3]) : "r"(a));
}
__device__ __forceinline__ void ldsm_x4_t(uint32_t* r, uint32_t a) {
    asm volatile("ldmatrix.sync.aligned.m8n8.x4.trans.shared.b16 {%0,%1,%2,%3}, [%4];"
                 : "=r"(r[0]), "=r"(r[1]), "=r"(r[2]), "=r"(r[3]) : "r"(a));
}
__device__ __forceinline__ void mma16816(float* c, const uint32_t* a, const uint32_t* b) {
    asm volatile("mma.sync.aligned.m16n8k16.row.col.f32.f16.f16.f32 "
                 "{%0,%1,%2,%3},{%4,%5,%6,%7},{%8,%9},{%0,%1,%2,%3};"
                 : "+f"(c[0]), "+f"(c[1]), "+f"(c[2]), "+f"(c[3])
                 : "r"(a[0]), "r"(a[1]), "r"(a[2]), "r"(a[3]), "r"(b[0]), "r"(b[1]));
}

extern __shared__ __align__(16) unsigned char g_smem[];

__global__ void init_kernel() {
    if (threadIdx.x < NCHUNK) g_ctr[threadIdx.x] = 0;
}

__device__ __forceinline__ void gemm_role(
    const float* __restrict__ A, const float* __restrict__ Bk,
    const float* __restrict__ bias, float* __restrict__ C,
    int chunk, int g)
{
    __half* As = reinterpret_cast<__half*>(g_smem);
    __half* Bs = reinterpret_cast<__half*>(g_smem + TILE_BYTES);

    const int tid  = threadIdx.x;
    const int lane = tid & 31;
    const int wid  = tid >> 5;
    const int m0 = chunk * M_PER_CHUNK + (g >> 4) * BM;
    const int n0 = (g & 15) * BN;
    const int wm = (wid & 3) * 32;
    const int wn = (wid >> 2) * 64;
    const int lrow = tid >> 5;
    const int lcol = tid & 31;

    // ---- B tile: global [k][2048] -> Bs[k][n] fp16 (exact: kernel is +/-1)
    #pragma unroll
    for (int r = 0; r < 16; ++r) {
        int k = r * 8 + lrow;
        float4 v = *reinterpret_cast<const float4*>(Bk + (size_t)k * U_UNITS + n0 + lcol * 4);
        __half2 p0 = __floats2half2_rn(v.x, v.y);
        __half2 p1 = __floats2half2_rn(v.z, v.w);
        *reinterpret_cast<__half2*>(Bs + k * SSTRIDE + lcol * 4)     = p0;
        *reinterpret_cast<__half2*>(Bs + k * SSTRIDE + lcol * 4 + 2) = p1;
    }
    // ---- A tile: fp32 -> fp16
    #pragma unroll
    for (int r = 0; r < 16; ++r) {
        int m = r * 8 + lrow;
        float4 v = *reinterpret_cast<const float4*>(A + (size_t)(m0 + m) * D_INPUT + lcol * 4);
        __half2 p0 = __floats2half2_rn(v.x, v.y);
        __half2 p1 = __floats2half2_rn(v.z, v.w);
        *reinterpret_cast<__half2*>(As + m * SSTRIDE + lcol * 4)     = p0;
        *reinterpret_cast<__half2*>(As + m * SSTRIDE + lcol * 4 + 2) = p1;
    }

    float acc[2][8][4];
    #pragma unroll
    for (int i = 0; i < 2; ++i)
        #pragma unroll
        for (int j = 0; j < 8; ++j)
            #pragma unroll
            for (int q = 0; q < 4; ++q) acc[i][j][q] = 0.0f;

    __syncthreads();

    #pragma unroll
    for (int kk = 0; kk < 8; ++kk) {
        uint32_t afr[2][4];
        #pragma unroll
        for (int mi = 0; mi < 2; ++mi) {
            int row = wm + mi * 16 + (lane & 15);
            int col = kk * 16 + ((lane >> 4) << 3);
            ldsm_x4(afr[mi], smem_u32(As + row * SSTRIDE + col));
        }
        #pragma unroll
        for (int np = 0; np < 4; ++np) {
            uint32_t bfr[4];
            int kr = kk * 16 + (lane & 7) + (lane & 8);
            int nc = wn + np * 16 + ((lane & 16) >> 1);
            ldsm_x4_t(bfr, smem_u32(Bs + kr * SSTRIDE + nc));
            #pragma unroll
            for (int mi = 0; mi < 2; ++mi) {
                mma16816(acc[mi][2 * np],     afr[mi], bfr);
                mma16816(acc[mi][2 * np + 1], afr[mi], bfr + 2);
            }
        }
    }

    // ---- epilogue: + bias (fp32), fp32 out
    #pragma unroll
    for (int mi = 0; mi < 2; ++mi) {
        #pragma unroll
        for (int ni = 0; ni < 8; ++ni) {
            int row = m0 + wm + mi * 16 + (lane >> 2);
            int col = n0 + wn + ni * 8 + (lane & 3) * 2;
            float b0 = __ldg(bias + col);
            float b1 = __ldg(bias + col + 1);
            float2 v0 = make_float2(acc[mi][ni][0] + b0, acc[mi][ni][1] + b1);
            float2 v1 = make_float2(acc[mi][ni][2] + b0, acc[mi][ni][3] + b1);
            *reinterpret_cast<float2*>(C + (size_t)row * U_UNITS + col)       = v0;
            *reinterpret_cast<float2*>(C + (size_t)(row + 8) * U_UNITS + col) = v1;
        }
    }

    // ---- signal chunk completion (release)
    __syncthreads();
    __threadfence();
    if (threadIdx.x == 0) atomicAdd(&g_ctr[chunk], 1);
}

// ======================= Scan role =======================
// Diagonal chains: h_t[u] depends only on h_{t-1}[u-1]; chain c of batch b visits
// unit (c+t) mod 2048 at step t. 8192 independent chains per chunk, one/thread.
__device__ __forceinline__ void scan_role(
    const float* __restrict__ h0, float* __restrict__ out, int chunk, int s)
{
    // wait for this chunk's GEMM (acquire)
    if (threadIdx.x == 0) {
        while (*(volatile int*)&g_ctr[chunk] < GEMM_PER_CHUNK) __nanosleep(64);
    }
    __syncthreads();
    __threadfence();

    const int gid = s * 256 + threadIdx.x;            // 0..8191 within chunk
    const int b = chunk * B_PER_CHUNK + (gid >> 11);
    const int c = gid & (U_UNITS - 1);

    float h = h0[(b << 11) | ((c + U_UNITS - 1) & (U_UNITS - 1))];
    float* base = out + (size_t)b * (T_STEPS * U_UNITS);

    float* lp = base; int lo = c;
    float* sp = base; int so = c;

    float vA[16], vB[16];
#define LOAD16(v)                                                   \
    { _Pragma("unroll") for (int j = 0; j < 16; ++j) {              \
        (v)[j] = __ldcs(lp + lo);                                   \
        lp += U_UNITS; lo = (lo + 1) & (U_UNITS - 1); } }
#define COMP16(v)                                                   \
    { _Pragma("unroll") for (int j = 0; j < 16; ++j) {              \
        float x = fmaf(RHO_C, h, (v)[j]);                           \
        asm("tanh.approx.f32 %0, %1;" : "=f"(h) : "f"(x));          \
        __stcs(sp + so, h);                                         \
        sp += U_UNITS; so = (so + 1) & (U_UNITS - 1); } }

    LOAD16(vA);
    for (int t = 0; t < T_STEPS; t += 32) {
        LOAD16(vB);
        COMP16(vA);
        if (t + 32 < T_STEPS) { LOAD16(vA); }
        COMP16(vB);
    }
#undef LOAD16
#undef COMP16
}

// ======================= fused persistent kernel =======================
// Block order per chunk: 256 GEMM blocks, then 32 scan blocks. In-order wave
// scheduling puts each chunk's scan right behind its GEMM; scan spin-waits on
// the chunk counter. Deadlock-free: flags depend only on GEMM blocks, and scan
// blocks can occupy at most 256 of ~296 resident slots.
__global__ __launch_bounds__(256, 2) void fused_kernel(
    const float* __restrict__ A, const float* __restrict__ Bk,
    const float* __restrict__ bias, const float* __restrict__ h0,
    float* __restrict__ out)
{
    const int bid = blockIdx.x;
    const int chunk = bid / BLK_PER_CHUNK;
    const int r = bid - chunk * BLK_PER_CHUNK;
    if (r < GEMM_PER_CHUNK) {
        gemm_role(A, Bk, bias, out, chunk, r);
    } else {
        scan_role(h0, out, chunk, r - GEMM_PER_CHUNK);
    }
}

// ======================= launch =======================
extern "C" void kernel_launch(void* const* d_in, const int* in_sizes, int n_in,
                              void* d_out, int out_size)
{
    const float* inputs = nullptr;
    const float* h0     = nullptr;
    const float* kern   = nullptr;
    const float* bias   = nullptr;
    for (int i = 0; i < n_in; ++i) {
        switch (in_sizes[i]) {
            case B_BATCH * T_STEPS * D_INPUT: inputs = (const float*)d_in[i]; break;
            case B_BATCH * U_UNITS:           h0     = (const float*)d_in[i]; break;
            case D_INPUT * U_UNITS:           kern   = (const float*)d_in[i]; break;
            case U_UNITS:                     bias   = (const float*)d_in[i]; break;
        }
    }
    float* out = (float*)d_out;

    const size_t smem_bytes = 2 * TILE_BYTES;   // 69632 B
    cudaFuncSetAttribute((const void*)fused_kernel,
                         cudaFuncAttributeMaxDynamicSharedMemorySize, (int)smem_bytes);

    init_kernel<<<1, NCHUNK>>>();
    fused_kernel<<<NCHUNK * BLK_PER_CHUNK, 256, smem_bytes>>>(inputs, kern, bias, h0, out);
}

// round 17
// speedup vs baseline: 1.3274x; 1.3274x over previous
#include <cuda_runtime.h>
#include <cuda_fp16.h>
#include <cstdint>

#define U_UNITS 2048
#define T_STEPS 512
#define B_BATCH 32
#define D_INPUT 128
#define M_TOTAL (B_BATCH * T_STEPS)   // 16384
#define RHO_C   0.99f

// fp16 u scratch (static device global: allocation rules allow this). 64 MB.
__device__ __half g_u[(size_t)M_TOTAL * U_UNITS];

// ======================= GEMM (u = inputs @ kernel + bias, fp16 out) ==============
// M = 16384, K = 128, N = 2048. Single-pass fp16 HMMA; u stored as fp16.
#define BM 128
#define BN 128
#define SSTRIDE 136                       // fp16 elems per smem row (128 + 8 pad)
#define TILE_BYTES (128 * SSTRIDE * 2)    // 34816 B

__device__ __forceinline__ uint32_t smem_u32(const void* p) {
    return (uint32_t)__cvta_generic_to_shared(p);
}
__device__ __forceinline__ void ldsm_x4(uint32_t* r, uint32_t a) {
    asm volatile("ldmatrix.sync.aligned.m8n8.x4.shared.b16 {%0,%1,%2,%3}, [%4];"
                 : "=r"(r[0]), "=r"(r[1]), "=r"(r[2]), "=r"(r[3]) : "r"(a));
}
__device__ __forceinline__ void ldsm_x4_t(uint32_t* r, uint32_t a) {
    asm volatile("ldmatrix.sync.aligned.m8n8.x4.trans.shared.b16 {%0,%1,%2,%3}, [%4];"
                 : "=r"(r[0]), "=r"(r[1]), "=r"(r[2]), "=r"(r[3]) : "r"(a));
}
__device__ __forceinline__ void mma16816(float* c, const uint32_t* a, const uint32_t* b) {
    asm volatile("mma.sync.aligned.m16n8k16.row.col.f32.f16.f16.f32 "
                 "{%0,%1,%2,%3},{%4,%5,%6,%7},{%8,%9},{%0,%1,%2,%3};"
                 : "+f"(c[0]), "+f"(c[1]), "+f"(c[2]), "+f"(c[3])
                 : "r"(a[0]), "r"(a[1]), "r"(a[2]), "r"(a[3]), "r"(b[0]), "r"(b[1]));
}

extern __shared__ __align__(16) unsigned char g_smem[];

__global__ __launch_bounds__(256, 2) void gemm_bias_kernel(
    const float* __restrict__ A,      // [16384, 128]
    const float* __restrict__ Bk,     // [128, 2048]
    const float* __restrict__ bias)   // [2048]
{
    __half* As = reinterpret_cast<__half*>(g_smem);
    __half* Bs = reinterpret_cast<__half*>(g_smem + TILE_BYTES);

    const int tid  = threadIdx.x;
    const int lane = tid & 31;
    const int wid  = tid >> 5;
    const int m0 = blockIdx.y * BM;
    const int n0 = blockIdx.x * BN;
    const int wm = (wid & 3) * 32;    // warp row offset (4 warps in M)
    const int wn = (wid >> 2) * 64;   // warp col offset (2 warps in N)

    const int lrow = tid >> 5;        // 0..7  (row within 8-row group)
    const int lcol = tid & 31;        // float4 column 0..31

    // ---- B tile: global [k][2048] -> Bs[k][n] fp16 (exact: kernel is +/-1)
    #pragma unroll
    for (int r = 0; r < 16; ++r) {
        int k = r * 8 + lrow;
        float4 v = *reinterpret_cast<const float4*>(Bk + (size_t)k * U_UNITS + n0 + lcol * 4);
        __half2 p0 = __floats2half2_rn(v.x, v.y);
        __half2 p1 = __floats2half2_rn(v.z, v.w);
        *reinterpret_cast<__half2*>(Bs + k * SSTRIDE + lcol * 4)     = p0;
        *reinterpret_cast<__half2*>(Bs + k * SSTRIDE + lcol * 4 + 2) = p1;
    }
    // ---- A tile: fp32 -> fp16 (single pass)
    #pragma unroll
    for (int r = 0; r < 16; ++r) {
        int m = r * 8 + lrow;
        float4 v = *reinterpret_cast<const float4*>(A + (size_t)(m0 + m) * D_INPUT + lcol * 4);
        __half2 p0 = __floats2half2_rn(v.x, v.y);
        __half2 p1 = __floats2half2_rn(v.z, v.w);
        *reinterpret_cast<__half2*>(As + m * SSTRIDE + lcol * 4)     = p0;
        *reinterpret_cast<__half2*>(As + m * SSTRIDE + lcol * 4 + 2) = p1;
    }

    float acc[2][8][4];
    #pragma unroll
    for (int i = 0; i < 2; ++i)
        #pragma unroll
        for (int j = 0; j < 8; ++j)
            #pragma unroll
            for (int q = 0; q < 4; ++q) acc[i][j][q] = 0.0f;

    __syncthreads();   // tiles ready; one barrier total

    #pragma unroll
    for (int kk = 0; kk < 8; ++kk) {
        uint32_t afr[2][4];
        #pragma unroll
        for (int mi = 0; mi < 2; ++mi) {
            int row = wm + mi * 16 + (lane & 15);
            int col = kk * 16 + ((lane >> 4) << 3);
            ldsm_x4(afr[mi], smem_u32(As + row * SSTRIDE + col));
        }
        #pragma unroll
        for (int np = 0; np < 4; ++np) {
            uint32_t bfr[4];
            int kr = kk * 16 + (lane & 7) + (lane & 8);       // +8 k rows for lanes 8-15/24-31
            int nc = wn + np * 16 + ((lane & 16) >> 1);       // +8 n cols for lanes 16-31
            ldsm_x4_t(bfr, smem_u32(Bs + kr * SSTRIDE + nc));
            #pragma unroll
            for (int mi = 0; mi < 2; ++mi) {
                mma16816(acc[mi][2 * np],     afr[mi], bfr);
                mma16816(acc[mi][2 * np + 1], afr[mi], bfr + 2);
            }
        }
    }

    // ---- epilogue: + bias (fp32 add), round to fp16, store to u scratch
    #pragma unroll
    for (int mi = 0; mi < 2; ++mi) {
        #pragma unroll
        for (int ni = 0; ni < 8; ++ni) {
            int row = m0 + wm + mi * 16 + (lane >> 2);
            int col = n0 + wn + ni * 8 + (lane & 3) * 2;
            float b0 = __ldg(bias + col);
            float b1 = __ldg(bias + col + 1);
            __half2 v0 = __floats2half2_rn(acc[mi][ni][0] + b0, acc[mi][ni][1] + b1);
            __half2 v1 = __floats2half2_rn(acc[mi][ni][2] + b0, acc[mi][ni][3] + b1);
            *reinterpret_cast<__half2*>(g_u + (size_t)row * U_UNITS + col)       = v0;
            *reinterpret_cast<__half2*>(g_u + (size_t)(row + 8) * U_UNITS + col) = v1;
        }
    }
}

// ======================= Scan: pipelined diagonal chains =======================
// h_t[u] depends only on h_{t-1}[u-1]: chain c visits unit (c+t) mod 2048 at step
// t => B*U = 65536 fully independent chains, one per thread, zero synchronization.
// Reads fp16 u (half the round-12 read traffic), writes fp32 h to d_out.
// 16+16 double buffer keeps next group's loads in flight during the dependent
// tanh chain of the current group.
__global__ __launch_bounds__(256) void scan_kernel(
    const float* __restrict__ h0, float* __restrict__ out)
{
    const int gid = blockIdx.x * 256 + threadIdx.x;   // 0..65535
    const int b = gid >> 11;
    const int c = gid & (U_UNITS - 1);

    float h = h0[(b << 11) | ((c + U_UNITS - 1) & (U_UNITS - 1))];
    const __half* ubase = g_u + (size_t)(b * T_STEPS) * U_UNITS;
    float* obase = out + (size_t)b * (T_STEPS * U_UNITS);

    const __half* lp = ubase; int lo = c;   // load cursor
    float* sp = obase;        int so = c;   // store cursor

    __half vA[16], vB[16];
#define LOAD16(v)                                                   \
    { _Pragma("unroll") for (int j = 0; j < 16; ++j) {              \
        (v)[j] = __ldcs(lp + lo);                                   \
        lp += U_UNITS; lo = (lo + 1) & (U_UNITS - 1); } }
#define COMP16(v)                                                   \
    { _Pragma("unroll") for (int j = 0; j < 16; ++j) {              \
        float x = fmaf(RHO_C, h, __half2float((v)[j]));             \
        asm("tanh.approx.f32 %0, %1;" : "=f"(h) : "f"(x));          \
        __stcs(sp + so, h);                                         \
        sp += U_UNITS; so = (so + 1) & (U_UNITS - 1); } }

    LOAD16(vA);
    for (int t = 0; t < T_STEPS; t += 32) {
        LOAD16(vB);                               // rows t+16 .. t+31
        COMP16(vA);                               // rows t    .. t+15
        if (t + 32 < T_STEPS) { LOAD16(vA); }     // rows t+32 .. t+47
        COMP16(vB);                               // rows t+16 .. t+31
    }
#undef LOAD16
#undef COMP16
}

// ======================= launch =======================
extern "C" void kernel_launch(void* const* d_in, const int* in_sizes, int n_in,
                              void* d_out, int out_size)
{
    const float* inputs = nullptr;
    const float* h0     = nullptr;
    const float* kern   = nullptr;
    const float* bias   = nullptr;
    for (int i = 0; i < n_in; ++i) {
        switch (in_sizes[i]) {
            case B_BATCH * T_STEPS * D_INPUT: inputs = (const float*)d_in[i]; break; // 2097152
            case B_BATCH * U_UNITS:           h0     = (const float*)d_in[i]; break; // 65536
            case D_INPUT * U_UNITS:           kern   = (const float*)d_in[i]; break; // 262144
            case U_UNITS:                     bias   = (const float*)d_in[i]; break; // 2048
        }
    }
    float* out = (float*)d_out;

    const size_t smem_bytes = 2 * TILE_BYTES;   // 69632 B
    cudaFuncSetAttribute((const void*)gemm_bias_kernel,
                         cudaFuncAttributeMaxDynamicSharedMemorySize, (int)smem_bytes);

    dim3 grid(U_UNITS / BN, M_TOTAL / BM);   // (16, 128)
    gemm_bias_kernel<<<grid, 256, smem_bytes>>>(inputs, kern, bias);
    scan_kernel<<<(B_BATCH * U_UNITS) / 256, 256>>>(h0, out);
}